// round 4
// baseline (speedup 1.0000x reference)
#include <cuda_runtime.h>
#include <cuda_bf16.h>
#include <cstdint>

#define KDIM 256

// ---------- helpers ----------
__device__ __forceinline__ uint32_t pk(float a, float b) {
    return ((uint32_t)__bfloat16_as_ushort(__float2bfloat16_rn(b)) << 16) |
           (uint32_t)__bfloat16_as_ushort(__float2bfloat16_rn(a));
}
__device__ __forceinline__ void bsplit2(float a, float b, uint32_t& hi, uint32_t& lo) {
    __nv_bfloat16 ah = __float2bfloat16_rn(a), bh = __float2bfloat16_rn(b);
    hi = ((uint32_t)__bfloat16_as_ushort(bh) << 16) | (uint32_t)__bfloat16_as_ushort(ah);
    lo = pk(a - __bfloat162float(ah), b - __bfloat162float(bh));
}
__device__ __forceinline__ void mma16816(float* c, const uint32_t* a, uint32_t b0, uint32_t b1) {
    asm volatile(
        "mma.sync.aligned.m16n8k16.row.col.f32.bf16.bf16.f32 "
        "{%0,%1,%2,%3},{%4,%5,%6,%7},{%8,%9},{%0,%1,%2,%3};"
        : "+f"(c[0]), "+f"(c[1]), "+f"(c[2]), "+f"(c[3])
        : "r"(a[0]), "r"(a[1]), "r"(a[2]), "r"(a[3]), "r"(b0), "r"(b1));
}

// SMEM layout (bytes)
#define SM_W1F 0          // uint4[16 kb][16 nb][32 lane]  = 131072
#define SM_W2F 131072     // uint4[4 m][2 kb][4 nb][32]    = 16384
#define SM_W3F 147456     // 16384
#define SM_B1  163840
#define SM_B2  164352
#define SM_B3  164864
#define SM_WF  165376
#define SM_BFV 165504
#define SMEM_BYTES 165632

extern __shared__ char smem[];

__global__ void __launch_bounds__(256, 1)
moe_kernel(const float* __restrict__ x,  const float* __restrict__ c1,
           const float* __restrict__ c2, const float* __restrict__ c3,
           const float* __restrict__ W1, const float* __restrict__ b1,
           const float* __restrict__ W2, const float* __restrict__ b2,
           const float* __restrict__ W3, const float* __restrict__ b3,
           const float* __restrict__ Wf, const float* __restrict__ bfp,
           float* __restrict__ out, int Btot) {
    const int tid = threadIdx.x;
    const int wid = tid >> 5;
    const int lane = tid & 31;
    const int g = lane >> 2;   // group id (row within m16 block)
    const int t = lane & 3;    // thread-in-group (col pair)

    uint4* w1f = (uint4*)(smem + SM_W1F);
    uint4* w2f = (uint4*)(smem + SM_W2F);
    uint4* w3f = (uint4*)(smem + SM_W3F);
    float* b1s = (float*)(smem + SM_B1);
    float* b2s = (float*)(smem + SM_B2);
    float* b3s = (float*)(smem + SM_B3);
    float* wfs = (float*)(smem + SM_WF);
    float* bfs = (float*)(smem + SM_BFV);

    // ---- pack W1 into per-lane B fragments: B(k,j) = W1[j*256+k], j=nb*8+g, k=kb*16+t*2 ----
    for (int e = wid; e < 256; e += 8) {
        int kb = e >> 4, nb = e & 15;
        const float* wp = W1 + (nb * 8 + g) * 256 + kb * 16 + t * 2;
        uint32_t b0h, b0l, b1h, b1l;
        bsplit2(wp[0], wp[1], b0h, b0l);
        bsplit2(wp[8], wp[9], b1h, b1l);
        w1f[e * 32 + lane] = make_uint4(b0h, b1h, b0l, b1l);
    }
    // ---- W2/W3: per expert m, B(h,kout)=W[m][kout][h]; kout=nb*8+g, h=kb*16+t*2 ----
    for (int e = wid; e < 32; e += 8) {
        int m = e >> 3, kb = (e >> 2) & 1, nb = e & 3;
        int off = (m * 32 + nb * 8 + g) * 32 + kb * 16 + t * 2;
        {
            const float* wp = W2 + off;
            uint32_t b0h, b0l, b1h, b1l;
            bsplit2(wp[0], wp[1], b0h, b0l);
            bsplit2(wp[8], wp[9], b1h, b1l);
            w2f[e * 32 + lane] = make_uint4(b0h, b1h, b0l, b1l);
        }
        {
            const float* wp = W3 + off;
            uint32_t b0h, b0l, b1h, b1l;
            bsplit2(wp[0], wp[1], b0h, b0l);
            bsplit2(wp[8], wp[9], b1h, b1l);
            w3f[e * 32 + lane] = make_uint4(b0h, b1h, b0l, b1l);
        }
    }
    if (tid < 128) { b1s[tid] = b1[tid]; b2s[tid] = b2[tid]; b3s[tid] = b3[tid]; }
    if (tid < 32) wfs[tid] = Wf[tid];
    if (tid == 0) bfs[0] = bfp[0];
    __syncthreads();

    float wfv[4][2];
#pragma unroll
    for (int nb = 0; nb < 4; nb++) { wfv[nb][0] = wfs[nb * 8 + t * 2]; wfv[nb][1] = wfs[nb * 8 + t * 2 + 1]; }
    const float bf0 = bfs[0];

    const int gw = blockIdx.x * 8 + wid;
    const int nunits = (Btot + 15) >> 4;

    for (int u = gw; u < nunits; u += gridDim.x * 8) {
        int r0 = u * 16 + g;
        int r1 = r0 + 8;
        int r0c = r0 < Btot ? r0 : Btot - 1;
        int r1c = r1 < Btot ? r1 : Btot - 1;
        const float* p0 = x + (size_t)r0c * KDIM + t * 2;
        const float* p1 = x + (size_t)r1c * KDIM + t * 2;

        // c1 coeffs for this thread's two rows
        float c1c0[16], c1c1[16];
        {
            const float4* a = (const float4*)(c1 + (size_t)r0c * 16);
            const float4* b = (const float4*)(c1 + (size_t)r1c * 16);
#pragma unroll
            for (int q = 0; q < 4; q++) {
                float4 v = a[q];
                c1c0[4 * q] = v.x; c1c0[4 * q + 1] = v.y; c1c0[4 * q + 2] = v.z; c1c0[4 * q + 3] = v.w;
                float4 w = b[q];
                c1c1[4 * q] = w.x; c1c1[4 * q + 1] = w.y; c1c1[4 * q + 2] = w.z; c1c1[4 * q + 3] = w.w;
            }
        }

        // ---- stage 1: C1[16 rows x 128 cols] ----
        float c1f[16][4];
#pragma unroll
        for (int nb = 0; nb < 16; nb++)
#pragma unroll
            for (int i = 0; i < 4; i++) c1f[nb][i] = 0.f;

        float2 xb[2][4];
#pragma unroll
        for (int pb = 0; pb < 2; pb++) {
            xb[pb][0] = *(const float2*)(p0 + pb * 16);
            xb[pb][1] = *(const float2*)(p0 + pb * 16 + 8);
            xb[pb][2] = *(const float2*)(p1 + pb * 16);
            xb[pb][3] = *(const float2*)(p1 + pb * 16 + 8);
        }
#pragma unroll
        for (int kb = 0; kb < 16; kb++) {
            uint32_t ah[4], al[4];
            // a0:(r0,klo) a1:(r1,klo) a2:(r0,khi) a3:(r1,khi)
            bsplit2(xb[kb & 1][0].x, xb[kb & 1][0].y, ah[0], al[0]);
            bsplit2(xb[kb & 1][2].x, xb[kb & 1][2].y, ah[1], al[1]);
            bsplit2(xb[kb & 1][1].x, xb[kb & 1][1].y, ah[2], al[2]);
            bsplit2(xb[kb & 1][3].x, xb[kb & 1][3].y, ah[3], al[3]);
            if (kb < 14) {
                xb[kb & 1][0] = *(const float2*)(p0 + (kb + 2) * 16);
                xb[kb & 1][1] = *(const float2*)(p0 + (kb + 2) * 16 + 8);
                xb[kb & 1][2] = *(const float2*)(p1 + (kb + 2) * 16);
                xb[kb & 1][3] = *(const float2*)(p1 + (kb + 2) * 16 + 8);
            }
            const uint4* wrow = w1f + kb * 16 * 32 + lane;
#pragma unroll
            for (int nb = 0; nb < 16; nb++) {
                uint4 w = wrow[nb * 32];
                mma16816(c1f[nb], ah, w.x, w.y);   // hi * Whi
                mma16816(c1f[nb], ah, w.z, w.w);   // hi * Wlo
                mma16816(c1f[nb], al, w.x, w.y);   // lo * Whi
            }
        }

        // ---- mix1: relu(+b1), c1-mix -> A2 fragments (register-local) ----
        uint32_t a2h[4][2][4], a2l[4][2][4];
#pragma unroll
        for (int hc = 0; hc < 4; hc++) {
            float o0[4][2], o1v[4][2];
#pragma unroll
            for (int n = 0; n < 4; n++) {
                int nb = n * 4 + hc;
                float bb0 = b1s[nb * 8 + t * 2], bb1 = b1s[nb * 8 + t * 2 + 1];
                o0[n][0]  = fmaxf(c1f[nb][0] + bb0, 0.f);
                o0[n][1]  = fmaxf(c1f[nb][1] + bb1, 0.f);
                o1v[n][0] = fmaxf(c1f[nb][2] + bb0, 0.f);
                o1v[n][1] = fmaxf(c1f[nb][3] + bb1, 0.f);
            }
            int kb2 = hc >> 1, hf = hc & 1;
#pragma unroll
            for (int m = 0; m < 4; m++) {
                float i00 = 0.f, i01 = 0.f, i10 = 0.f, i11 = 0.f;
#pragma unroll
                for (int n = 0; n < 4; n++) {
                    i00 = fmaf(o0[n][0],  c1c0[n * 4 + m], i00);
                    i01 = fmaf(o0[n][1],  c1c0[n * 4 + m], i01);
                    i10 = fmaf(o1v[n][0], c1c1[n * 4 + m], i10);
                    i11 = fmaf(o1v[n][1], c1c1[n * 4 + m], i11);
                }
                bsplit2(i00, i01, a2h[m][kb2][hf * 2 + 0], a2l[m][kb2][hf * 2 + 0]);
                bsplit2(i10, i11, a2h[m][kb2][hf * 2 + 1], a2l[m][kb2][hf * 2 + 1]);
            }
        }

        // c2 coeffs (issued before stage-2 mma; latency hidden)
        float c2c0[16], c2c1[16];
        {
            const float4* a = (const float4*)(c2 + (size_t)r0c * 16);
            const float4* b = (const float4*)(c2 + (size_t)r1c * 16);
#pragma unroll
            for (int q = 0; q < 4; q++) {
                float4 v = a[q];
                c2c0[4 * q] = v.x; c2c0[4 * q + 1] = v.y; c2c0[4 * q + 2] = v.z; c2c0[4 * q + 3] = v.w;
                float4 w = b[q];
                c2c1[4 * q] = w.x; c2c1[4 * q + 1] = w.y; c2c1[4 * q + 2] = w.z; c2c1[4 * q + 3] = w.w;
            }
        }

        // ---- stage 2 ----
        float c2f[4][4][4];
#pragma unroll
        for (int m = 0; m < 4; m++)
#pragma unroll
            for (int nb = 0; nb < 4; nb++)
#pragma unroll
                for (int i = 0; i < 4; i++) c2f[m][nb][i] = 0.f;
#pragma unroll
        for (int m = 0; m < 4; m++)
#pragma unroll
            for (int kb = 0; kb < 2; kb++)
#pragma unroll
                for (int nb = 0; nb < 4; nb++) {
                    uint4 w = w2f[((m * 2 + kb) * 4 + nb) * 32 + lane];
                    mma16816(c2f[m][nb], a2h[m][kb], w.x, w.y);
                    mma16816(c2f[m][nb], a2h[m][kb], w.z, w.w);
                    mma16816(c2f[m][nb], a2l[m][kb], w.x, w.y);
                }

        // ---- mix2 -> A3 ----
        uint32_t a3h[4][2][4], a3l[4][2][4];
#pragma unroll
        for (int hc = 0; hc < 4; hc++) {
            float o0[4][2], o1v[4][2];
#pragma unroll
            for (int n = 0; n < 4; n++) {
                float bb0 = b2s[n * 32 + hc * 8 + t * 2], bb1 = b2s[n * 32 + hc * 8 + t * 2 + 1];
                o0[n][0]  = fmaxf(c2f[n][hc][0] + bb0, 0.f);
                o0[n][1]  = fmaxf(c2f[n][hc][1] + bb1, 0.f);
                o1v[n][0] = fmaxf(c2f[n][hc][2] + bb0, 0.f);
                o1v[n][1] = fmaxf(c2f[n][hc][3] + bb1, 0.f);
            }
            int kb2 = hc >> 1, hf = hc & 1;
#pragma unroll
            for (int m = 0; m < 4; m++) {
                float i00 = 0.f, i01 = 0.f, i10 = 0.f, i11 = 0.f;
#pragma unroll
                for (int n = 0; n < 4; n++) {
                    i00 = fmaf(o0[n][0],  c2c0[n * 4 + m], i00);
                    i01 = fmaf(o0[n][1],  c2c0[n * 4 + m], i01);
                    i10 = fmaf(o1v[n][0], c2c1[n * 4 + m], i10);
                    i11 = fmaf(o1v[n][1], c2c1[n * 4 + m], i11);
                }
                bsplit2(i00, i01, a3h[m][kb2][hf * 2 + 0], a3l[m][kb2][hf * 2 + 0]);
                bsplit2(i10, i11, a3h[m][kb2][hf * 2 + 1], a3l[m][kb2][hf * 2 + 1]);
            }
        }

        // c3 coeffs
        float c3c0[4], c3c1[4];
        {
            float4 v = *(const float4*)(c3 + (size_t)r0c * 4);
            c3c0[0] = v.x; c3c0[1] = v.y; c3c0[2] = v.z; c3c0[3] = v.w;
            float4 w = *(const float4*)(c3 + (size_t)r1c * 4);
            c3c1[0] = w.x; c3c1[1] = w.y; c3c1[2] = w.z; c3c1[3] = w.w;
        }

        // ---- stage 3 ----
        float c3f[4][4][4];
#pragma unroll
        for (int m = 0; m < 4; m++)
#pragma unroll
            for (int nb = 0; nb < 4; nb++)
#pragma unroll
                for (int i = 0; i < 4; i++) c3f[m][nb][i] = 0.f;
#pragma unroll
        for (int m = 0; m < 4; m++)
#pragma unroll
            for (int kb = 0; kb < 2; kb++)
#pragma unroll
                for (int nb = 0; nb < 4; nb++) {
                    uint4 w = w3f[((m * 2 + kb) * 4 + nb) * 32 + lane];
                    mma16816(c3f[m][nb], a3h[m][kb], w.x, w.y);
                    mma16816(c3f[m][nb], a3h[m][kb], w.z, w.w);
                    mma16816(c3f[m][nb], a3l[m][kb], w.x, w.y);
                }

        // ---- final: relu(+b3), c3 mix, Wf dot, quad reduce ----
        float pa = 0.f, pb = 0.f;
#pragma unroll
        for (int nb = 0; nb < 4; nb++) {
#pragma unroll
            for (int n = 0; n < 4; n++) {
                float bb0 = b3s[n * 32 + nb * 8 + t * 2], bb1 = b3s[n * 32 + nb * 8 + t * 2 + 1];
                float q00 = fmaxf(c3f[n][nb][0] + bb0, 0.f);
                float q01 = fmaxf(c3f[n][nb][1] + bb1, 0.f);
                float q10 = fmaxf(c3f[n][nb][2] + bb0, 0.f);
                float q11 = fmaxf(c3f[n][nb][3] + bb1, 0.f);
                pa = fmaf(fmaf(q00, wfv[nb][0], q01 * wfv[nb][1]), c3c0[n], pa);
                pb = fmaf(fmaf(q10, wfv[nb][0], q11 * wfv[nb][1]), c3c1[n], pb);
            }
        }
        pa += __shfl_xor_sync(0xffffffffu, pa, 1);
        pa += __shfl_xor_sync(0xffffffffu, pa, 2);
        pb += __shfl_xor_sync(0xffffffffu, pb, 1);
        pb += __shfl_xor_sync(0xffffffffu, pb, 2);
        if (t == 0) {
            if (r0 < Btot) out[r0] = pa + bf0;
            if (r1 < Btot) out[r1] = pb + bf0;
        }
    }
}

extern "C" void kernel_launch(void* const* d_in, const int* in_sizes, int n_in,
                              void* d_out, int out_size) {
    const float* x   = (const float*)d_in[0];
    const float* c1  = (const float*)d_in[1];
    const float* c2  = (const float*)d_in[2];
    const float* c3  = (const float*)d_in[3];
    const float* W1  = (const float*)d_in[4];
    const float* b1  = (const float*)d_in[5];
    const float* W2  = (const float*)d_in[6];
    const float* b2  = (const float*)d_in[7];
    const float* W3  = (const float*)d_in[8];
    const float* b3  = (const float*)d_in[9];
    const float* Wf  = (const float*)d_in[10];
    const float* bfp = (const float*)d_in[11];
    int B = in_sizes[0] / KDIM;
    static bool configured = false;
    if (!configured) {
        cudaFuncSetAttribute(moe_kernel, cudaFuncAttributeMaxDynamicSharedMemorySize, SMEM_BYTES);
        configured = true;
    }
    moe_kernel<<<148, 256, SMEM_BYTES>>>(x, c1, c2, c3, W1, b1, W2, b2, W3, b3, Wf, bfp,
                                         (float*)d_out, B);
}

// round 5
// speedup vs baseline: 1.0097x; 1.0097x over previous
#include <cuda_runtime.h>
#include <cuda_bf16.h>
#include <cstdint>

#define KDIM 256
#define NWARP 12

// ---------- helpers ----------
__device__ __forceinline__ uint32_t pk(float a, float b) {
    return ((uint32_t)__bfloat16_as_ushort(__float2bfloat16_rn(b)) << 16) |
           (uint32_t)__bfloat16_as_ushort(__float2bfloat16_rn(a));
}
__device__ __forceinline__ void bsplit2(float a, float b, uint32_t& hi, uint32_t& lo) {
    __nv_bfloat16 ah = __float2bfloat16_rn(a), bh = __float2bfloat16_rn(b);
    hi = ((uint32_t)__bfloat16_as_ushort(bh) << 16) | (uint32_t)__bfloat16_as_ushort(ah);
    lo = pk(a - __bfloat162float(ah), b - __bfloat162float(bh));
}
__device__ __forceinline__ void mma16816(float* c, const uint32_t* a, uint32_t b0, uint32_t b1) {
    asm volatile(
        "mma.sync.aligned.m16n8k16.row.col.f32.bf16.bf16.f32 "
        "{%0,%1,%2,%3},{%4,%5,%6,%7},{%8,%9},{%0,%1,%2,%3};"
        : "+f"(c[0]), "+f"(c[1]), "+f"(c[2]), "+f"(c[3])
        : "r"(a[0]), "r"(a[1]), "r"(a[2]), "r"(a[3]), "r"(b0), "r"(b1));
}

// SMEM layout (bytes)
#define SM_W1F 0          // uint4[16 kb][16 nb][32 lane]  = 131072
#define SM_W2F 131072     // uint4[4 m][2 kb][4 nb][32]    = 16384
#define SM_W3F 147456     // 16384
#define SM_B1  163840
#define SM_B2  164352
#define SM_B3  164864
#define SM_WF  165376
#define SM_BFV 165504
#define SMEM_BYTES 165632

extern __shared__ char smem[];

__global__ void __launch_bounds__(32 * NWARP, 1)
moe_kernel(const float* __restrict__ x,  const float* __restrict__ c1,
           const float* __restrict__ c2, const float* __restrict__ c3,
           const float* __restrict__ W1, const float* __restrict__ b1,
           const float* __restrict__ W2, const float* __restrict__ b2,
           const float* __restrict__ W3, const float* __restrict__ b3,
           const float* __restrict__ Wf, const float* __restrict__ bfp,
           float* __restrict__ out, int Btot) {
    const int tid = threadIdx.x;
    const int wid = tid >> 5;
    const int lane = tid & 31;
    const int g = lane >> 2;   // group id (row within m16 block)
    const int t = lane & 3;    // thread-in-group (col pair)

    uint4* w1f = (uint4*)(smem + SM_W1F);
    uint4* w2f = (uint4*)(smem + SM_W2F);
    uint4* w3f = (uint4*)(smem + SM_W3F);
    float* b1s = (float*)(smem + SM_B1);
    float* b2s = (float*)(smem + SM_B2);
    float* b3s = (float*)(smem + SM_B3);
    float* wfs = (float*)(smem + SM_WF);
    float* bfs = (float*)(smem + SM_BFV);

    // ---- pack W1 into per-lane B fragments: B(k,j) = W1[j*256+k], j=nb*8+g, k=kb*16+t*2 ----
    for (int e = wid; e < 256; e += NWARP) {
        int kb = e >> 4, nb = e & 15;
        const float* wp = W1 + (nb * 8 + g) * 256 + kb * 16 + t * 2;
        uint32_t b0h, b0l, b1h, b1l;
        bsplit2(wp[0], wp[1], b0h, b0l);
        bsplit2(wp[8], wp[9], b1h, b1l);
        w1f[e * 32 + lane] = make_uint4(b0h, b1h, b0l, b1l);
    }
    // ---- W2/W3: per expert m, B(h,kout)=W[m][kout][h]; kout=nb*8+g, h=kb*16+t*2 ----
    for (int e = wid; e < 32; e += NWARP) {
        int m = e >> 3, kb = (e >> 2) & 1, nb = e & 3;
        int off = (m * 32 + nb * 8 + g) * 32 + kb * 16 + t * 2;
        {
            const float* wp = W2 + off;
            uint32_t b0h, b0l, b1h, b1l;
            bsplit2(wp[0], wp[1], b0h, b0l);
            bsplit2(wp[8], wp[9], b1h, b1l);
            w2f[e * 32 + lane] = make_uint4(b0h, b1h, b0l, b1l);
        }
        {
            const float* wp = W3 + off;
            uint32_t b0h, b0l, b1h, b1l;
            bsplit2(wp[0], wp[1], b0h, b0l);
            bsplit2(wp[8], wp[9], b1h, b1l);
            w3f[e * 32 + lane] = make_uint4(b0h, b1h, b0l, b1l);
        }
    }
    if (tid < 128) { b1s[tid] = b1[tid]; b2s[tid] = b2[tid]; b3s[tid] = b3[tid]; }
    if (tid < 32 && wid == 0) wfs[tid] = Wf[tid];
    if (tid == 0) bfs[0] = bfp[0];
    __syncthreads();

    float wfv[4][2];
#pragma unroll
    for (int nb = 0; nb < 4; nb++) { wfv[nb][0] = wfs[nb * 8 + t * 2]; wfv[nb][1] = wfs[nb * 8 + t * 2 + 1]; }
    const float bf0 = bfs[0];

    const int gw = blockIdx.x * NWARP + wid;
    const int nunits = (Btot + 15) >> 4;

    for (int u = gw; u < nunits; u += gridDim.x * NWARP) {
        int r0 = u * 16 + g;
        int r1 = r0 + 8;
        int r0c = r0 < Btot ? r0 : Btot - 1;
        int r1c = r1 < Btot ? r1 : Btot - 1;
        const float* p0 = x + (size_t)r0c * KDIM + t * 2;
        const float* p1 = x + (size_t)r1c * KDIM + t * 2;

        // c1 coeffs for this thread's two rows (prefetch; latency hidden by stage-1)
        float c1c0[16], c1c1[16];
        {
            const float4* a = (const float4*)(c1 + (size_t)r0c * 16);
            const float4* b = (const float4*)(c1 + (size_t)r1c * 16);
#pragma unroll
            for (int q = 0; q < 4; q++) {
                float4 v = a[q];
                c1c0[4 * q] = v.x; c1c0[4 * q + 1] = v.y; c1c0[4 * q + 2] = v.z; c1c0[4 * q + 3] = v.w;
                float4 w = b[q];
                c1c1[4 * q] = w.x; c1c1[4 * q + 1] = w.y; c1c1[4 * q + 2] = w.z; c1c1[4 * q + 3] = w.w;
            }
        }

        // ---- stage 1: C1[16 rows x 128 cols] ----
        float c1f[16][4];
#pragma unroll
        for (int nb = 0; nb < 16; nb++)
#pragma unroll
            for (int i = 0; i < 4; i++) c1f[nb][i] = 0.f;

        float2 xb[2][4];
#pragma unroll
        for (int pb = 0; pb < 2; pb++) {
            xb[pb][0] = *(const float2*)(p0 + pb * 16);
            xb[pb][1] = *(const float2*)(p0 + pb * 16 + 8);
            xb[pb][2] = *(const float2*)(p1 + pb * 16);
            xb[pb][3] = *(const float2*)(p1 + pb * 16 + 8);
        }
#pragma unroll
        for (int kb = 0; kb < 16; kb++) {
            uint32_t ah[4], al[4];
            // a0:(r0,klo) a1:(r1,klo) a2:(r0,khi) a3:(r1,khi)
            bsplit2(xb[kb & 1][0].x, xb[kb & 1][0].y, ah[0], al[0]);
            bsplit2(xb[kb & 1][2].x, xb[kb & 1][2].y, ah[1], al[1]);
            bsplit2(xb[kb & 1][1].x, xb[kb & 1][1].y, ah[2], al[2]);
            bsplit2(xb[kb & 1][3].x, xb[kb & 1][3].y, ah[3], al[3]);
            if (kb < 14) {
                xb[kb & 1][0] = *(const float2*)(p0 + (kb + 2) * 16);
                xb[kb & 1][1] = *(const float2*)(p0 + (kb + 2) * 16 + 8);
                xb[kb & 1][2] = *(const float2*)(p1 + (kb + 2) * 16);
                xb[kb & 1][3] = *(const float2*)(p1 + (kb + 2) * 16 + 8);
            }
            const uint4* wrow = w1f + kb * 16 * 32 + lane;
#pragma unroll
            for (int nb = 0; nb < 16; nb++) {
                uint4 w = wrow[nb * 32];
                mma16816(c1f[nb], ah, w.x, w.y);   // hi * Whi
                mma16816(c1f[nb], ah, w.z, w.w);   // hi * Wlo
                mma16816(c1f[nb], al, w.x, w.y);   // lo * Whi
            }
        }

        // ---- mix1: relu(+b1), c1-mix -> A2 fragments (register-local) ----
        uint32_t a2h[4][2][4], a2l[4][2][4];
#pragma unroll
        for (int hc = 0; hc < 4; hc++) {
            float o0[4][2], o1v[4][2];
#pragma unroll
            for (int n = 0; n < 4; n++) {
                int nb = n * 4 + hc;
                float bb0 = b1s[nb * 8 + t * 2], bb1 = b1s[nb * 8 + t * 2 + 1];
                o0[n][0]  = fmaxf(c1f[nb][0] + bb0, 0.f);
                o0[n][1]  = fmaxf(c1f[nb][1] + bb1, 0.f);
                o1v[n][0] = fmaxf(c1f[nb][2] + bb0, 0.f);
                o1v[n][1] = fmaxf(c1f[nb][3] + bb1, 0.f);
            }
            int kb2 = hc >> 1, hf = hc & 1;
#pragma unroll
            for (int m = 0; m < 4; m++) {
                float i00 = 0.f, i01 = 0.f, i10 = 0.f, i11 = 0.f;
#pragma unroll
                for (int n = 0; n < 4; n++) {
                    i00 = fmaf(o0[n][0],  c1c0[n * 4 + m], i00);
                    i01 = fmaf(o0[n][1],  c1c0[n * 4 + m], i01);
                    i10 = fmaf(o1v[n][0], c1c1[n * 4 + m], i10);
                    i11 = fmaf(o1v[n][1], c1c1[n * 4 + m], i11);
                }
                bsplit2(i00, i01, a2h[m][kb2][hf * 2 + 0], a2l[m][kb2][hf * 2 + 0]);
                bsplit2(i10, i11, a2h[m][kb2][hf * 2 + 1], a2l[m][kb2][hf * 2 + 1]);
            }
        }

        // ---- stage 2 ----
        float c2f[4][4][4];
#pragma unroll
        for (int m = 0; m < 4; m++)
#pragma unroll
            for (int nb = 0; nb < 4; nb++)
#pragma unroll
                for (int i = 0; i < 4; i++) c2f[m][nb][i] = 0.f;
#pragma unroll
        for (int m = 0; m < 4; m++)
#pragma unroll
            for (int kb = 0; kb < 2; kb++)
#pragma unroll
                for (int nb = 0; nb < 4; nb++) {
                    uint4 w = w2f[((m * 2 + kb) * 4 + nb) * 32 + lane];
                    mma16816(c2f[m][nb], a2h[m][kb], w.x, w.y);
                    mma16816(c2f[m][nb], a2h[m][kb], w.z, w.w);
                    mma16816(c2f[m][nb], a2l[m][kb], w.x, w.y);
                }

        // c2 coeffs loaded AFTER stage-2 mma (register-pressure: keeps stage-2 peak ~140)
        float c2c0[16], c2c1[16];
        {
            const float4* a = (const float4*)(c2 + (size_t)r0c * 16);
            const float4* b = (const float4*)(c2 + (size_t)r1c * 16);
#pragma unroll
            for (int q = 0; q < 4; q++) {
                float4 v = a[q];
                c2c0[4 * q] = v.x; c2c0[4 * q + 1] = v.y; c2c0[4 * q + 2] = v.z; c2c0[4 * q + 3] = v.w;
                float4 w = b[q];
                c2c1[4 * q] = w.x; c2c1[4 * q + 1] = w.y; c2c1[4 * q + 2] = w.z; c2c1[4 * q + 3] = w.w;
            }
        }

        // ---- mix2 -> A3 ----
        uint32_t a3h[4][2][4], a3l[4][2][4];
#pragma unroll
        for (int hc = 0; hc < 4; hc++) {
            float o0[4][2], o1v[4][2];
#pragma unroll
            for (int n = 0; n < 4; n++) {
                float bb0 = b2s[n * 32 + hc * 8 + t * 2], bb1 = b2s[n * 32 + hc * 8 + t * 2 + 1];
                o0[n][0]  = fmaxf(c2f[n][hc][0] + bb0, 0.f);
                o0[n][1]  = fmaxf(c2f[n][hc][1] + bb1, 0.f);
                o1v[n][0] = fmaxf(c2f[n][hc][2] + bb0, 0.f);
                o1v[n][1] = fmaxf(c2f[n][hc][3] + bb1, 0.f);
            }
            int kb2 = hc >> 1, hf = hc & 1;
#pragma unroll
            for (int m = 0; m < 4; m++) {
                float i00 = 0.f, i01 = 0.f, i10 = 0.f, i11 = 0.f;
#pragma unroll
                for (int n = 0; n < 4; n++) {
                    i00 = fmaf(o0[n][0],  c2c0[n * 4 + m], i00);
                    i01 = fmaf(o0[n][1],  c2c0[n * 4 + m], i01);
                    i10 = fmaf(o1v[n][0], c2c1[n * 4 + m], i10);
                    i11 = fmaf(o1v[n][1], c2c1[n * 4 + m], i11);
                }
                bsplit2(i00, i01, a3h[m][kb2][hf * 2 + 0], a3l[m][kb2][hf * 2 + 0]);
                bsplit2(i10, i11, a3h[m][kb2][hf * 2 + 1], a3l[m][kb2][hf * 2 + 1]);
            }
        }

        // ---- stage 3 ----
        float c3f[4][4][4];
#pragma unroll
        for (int m = 0; m < 4; m++)
#pragma unroll
            for (int nb = 0; nb < 4; nb++)
#pragma unroll
                for (int i = 0; i < 4; i++) c3f[m][nb][i] = 0.f;
#pragma unroll
        for (int m = 0; m < 4; m++)
#pragma unroll
            for (int kb = 0; kb < 2; kb++)
#pragma unroll
                for (int nb = 0; nb < 4; nb++) {
                    uint4 w = w3f[((m * 2 + kb) * 4 + nb) * 32 + lane];
                    mma16816(c3f[m][nb], a3h[m][kb], w.x, w.y);
                    mma16816(c3f[m][nb], a3h[m][kb], w.z, w.w);
                    mma16816(c3f[m][nb], a3l[m][kb], w.x, w.y);
                }

        // c3 coeffs
        float c3c0[4], c3c1[4];
        {
            float4 v = *(const float4*)(c3 + (size_t)r0c * 4);
            c3c0[0] = v.x; c3c0[1] = v.y; c3c0[2] = v.z; c3c0[3] = v.w;
            float4 w = *(const float4*)(c3 + (size_t)r1c * 4);
            c3c1[0] = w.x; c3c1[1] = w.y; c3c1[2] = w.z; c3c1[3] = w.w;
        }

        // ---- final: relu(+b3), c3 mix, Wf dot, quad reduce ----
        float pa = 0.f, pb = 0.f;
#pragma unroll
        for (int nb = 0; nb < 4; nb++) {
#pragma unroll
            for (int n = 0; n < 4; n++) {
                float bb0 = b3s[n * 32 + nb * 8 + t * 2], bb1 = b3s[n * 32 + nb * 8 + t * 2 + 1];
                float q00 = fmaxf(c3f[n][nb][0] + bb0, 0.f);
                float q01 = fmaxf(c3f[n][nb][1] + bb1, 0.f);
                float q10 = fmaxf(c3f[n][nb][2] + bb0, 0.f);
                float q11 = fmaxf(c3f[n][nb][3] + bb1, 0.f);
                pa = fmaf(fmaf(q00, wfv[nb][0], q01 * wfv[nb][1]), c3c0[n], pa);
                pb = fmaf(fmaf(q10, wfv[nb][0], q11 * wfv[nb][1]), c3c1[n], pb);
            }
        }
        pa += __shfl_xor_sync(0xffffffffu, pa, 1);
        pa += __shfl_xor_sync(0xffffffffu, pa, 2);
        pb += __shfl_xor_sync(0xffffffffu, pb, 1);
        pb += __shfl_xor_sync(0xffffffffu, pb, 2);
        if (t == 0) {
            if (r0 < Btot) out[r0] = pa + bf0;
            if (r1 < Btot) out[r1] = pb + bf0;
        }
    }
}

extern "C" void kernel_launch(void* const* d_in, const int* in_sizes, int n_in,
                              void* d_out, int out_size) {
    const float* x   = (const float*)d_in[0];
    const float* c1  = (const float*)d_in[1];
    const float* c2  = (const float*)d_in[2];
    const float* c3  = (const float*)d_in[3];
    const float* W1  = (const float*)d_in[4];
    const float* b1  = (const float*)d_in[5];
    const float* W2  = (const float*)d_in[6];
    const float* b2  = (const float*)d_in[7];
    const float* W3  = (const float*)d_in[8];
    const float* b3  = (const float*)d_in[9];
    const float* Wf  = (const float*)d_in[10];
    const float* bfp = (const float*)d_in[11];
    int B = in_sizes[0] / KDIM;
    static bool configured = false;
    if (!configured) {
        cudaFuncSetAttribute(moe_kernel, cudaFuncAttributeMaxDynamicSharedMemorySize, SMEM_BYTES);
        configured = true;
    }
    moe_kernel<<<148, 32 * NWARP, SMEM_BYTES>>>(x, c1, c2, c3, W1, b1, W2, b2, W3, b3, Wf, bfp,
                                                (float*)d_out, B);
}